// round 13
// baseline (speedup 1.0000x reference)
#include <cuda_runtime.h>
#include <cstdint>

#define BATCH 2048
#define IN_SZ 40960
#define HID 256
#define ROW_F4 (IN_SZ / 4)          // 10240 uint4 per one-hot row
#define ROW_ITERS (ROW_F4 / 256)    // 40 per perspective; 80 total per CTA
#define STAGES 6                    // cp.async ring depth (16B/thread/stage)

__device__ float g_ftw_t[(size_t)IN_SZ * HID];   // 41.9 MB transposed weights

#define CP_ASYNC16(dst_u32, src_ptr) \
    asm volatile("cp.async.cg.shared.global [%0], [%1], 16;" \
                 :: "r"(dst_u32), "l"(src_ptr) : "memory")
#define CP_COMMIT() asm volatile("cp.async.commit_group;" ::: "memory")
#define CP_WAIT5()  asm volatile("cp.async.wait_group 5;" ::: "memory")

// ---------------------------------------------------------------------------
// Kernel 1: transpose ft_w [256, 40960] -> g_ftw_t [40960, 256]
// ---------------------------------------------------------------------------
__global__ __launch_bounds__(256) void transpose_ft(const float* __restrict__ ft_w) {
    __shared__ float tile[32][33];
    int x = blockIdx.x * 32 + threadIdx.x;
    int y = blockIdx.y * 32 + threadIdx.y;
#pragma unroll
    for (int k = 0; k < 32; k += 8)
        tile[threadIdx.y + k][threadIdx.x] = ft_w[(size_t)(y + k) * IN_SZ + x];
    __syncthreads();
    int ox = blockIdx.y * 32 + threadIdx.x;
    int oy = blockIdx.x * 32 + threadIdx.y;
#pragma unroll
    for (int k = 0; k < 32; k += 8)
        g_ftw_t[(size_t)(oy + k) * HID + ox] = tile[threadIdx.x][threadIdx.y + k];
}

// ---------------------------------------------------------------------------
// Kernel 2: one CTA per row. Scan streams through a 6-stage cp.async smem
// ring (6 transfers in flight/thread, low regs -> 8 CTAs/SM). White gather
// interleaved into black scan; ring storage re-aliased as red/hid afterward.
// ---------------------------------------------------------------------------
__global__ __launch_bounds__(256, 8) void nnue_fused(
    const float* __restrict__ white, const float* __restrict__ black,
    const float* __restrict__ stm,
    const float* __restrict__ ft_b,
    const float* __restrict__ l1w, const float* __restrict__ l1b,
    const float* __restrict__ l2w, const float* __restrict__ l2b,
    const float* __restrict__ l3w, const float* __restrict__ l3b,
    float* __restrict__ out)
{
    __shared__ __align__(16) char pool[STAGES * 256 * 16];   // 24 KB ring, aliased later
    __shared__ int   cnt[2];
    __shared__ int   idx[2][32];
    __shared__ float x1s[32];
    __shared__ float x2s[32];

    const int b   = blockIdx.x;
    const int tid = threadIdx.x;

    if (tid < 2) cnt[tid] = 0;
    __syncthreads();

    uint4* buf = reinterpret_cast<uint4*>(pool);
    const uint4* wsrc = reinterpret_cast<const uint4*>(white) + (size_t)b * ROW_F4 + tid;
    const uint4* bsrc = reinterpret_cast<const uint4*>(black) + (size_t)b * ROW_F4 + tid;
    const unsigned int buf_base = (unsigned int)__cvta_generic_to_shared(pool);

    // prologue: fill the ring (flat it: [0,40) white, [40,80) black)
#pragma unroll
    for (int s = 0; s < STAGES; ++s) {
        const uint4* src = (s < ROW_ITERS) ? (wsrc + s * 256) : (bsrc + (s - ROW_ITERS) * 256);
        CP_ASYNC16(buf_base + (((s % STAGES) * 256 + tid) << 4), src);
        CP_COMMIT();
    }

    // ---- white scan ----
    for (int it = 0; it < ROW_ITERS; ++it) {
        CP_WAIT5();
        uint4 v = buf[(it % STAGES) * 256 + tid];
        if (v.x | v.y | v.z | v.w) {
            int base = (it * 256 + tid) * 4;
            if (v.x) { int s = atomicAdd(&cnt[0], 1); idx[0][s] = base + 0; }
            if (v.y) { int s = atomicAdd(&cnt[0], 1); idx[0][s] = base + 1; }
            if (v.z) { int s = atomicAdd(&cnt[0], 1); idx[0][s] = base + 2; }
            if (v.w) { int s = atomicAdd(&cnt[0], 1); idx[0][s] = base + 3; }
        }
        int nx = it + STAGES;   // nx in [6,46) < 80 always here
        const uint4* src = (nx < ROW_ITERS) ? (wsrc + nx * 256) : (bsrc + (nx - ROW_ITERS) * 256);
        CP_ASYNC16(buf_base + (((nx % STAGES) * 256 + tid) << 4), src);
        CP_COMMIT();
    }
    __syncthreads();
    const int wc = cnt[0];

    const int c  = tid & 63;
    const int fg = tid >> 6;
    const float4* __restrict__ ftw4 = reinterpret_cast<const float4*>(g_ftw_t);

    float4 aw = make_float4(0.f, 0.f, 0.f, 0.f);
    float4 ab = make_float4(0.f, 0.f, 0.f, 0.f);

    // ---- black scan, white gather interleaved ----
    for (int it = ROW_ITERS; it < 2 * ROW_ITERS; ++it) {
        CP_WAIT5();
        uint4 v = buf[(it % STAGES) * 256 + tid];
        int g = it - ROW_ITERS;
        if (g < 8) {
            int k = fg + 4 * g;
            if (k < wc) {
                float4 t = ftw4[(size_t)idx[0][k] * 64 + c];
                aw.x += t.x; aw.y += t.y; aw.z += t.z; aw.w += t.w;
            }
        }
        if (v.x | v.y | v.z | v.w) {
            int base = ((it - ROW_ITERS) * 256 + tid) * 4;
            if (v.x) { int s = atomicAdd(&cnt[1], 1); idx[1][s] = base + 0; }
            if (v.y) { int s = atomicAdd(&cnt[1], 1); idx[1][s] = base + 1; }
            if (v.z) { int s = atomicAdd(&cnt[1], 1); idx[1][s] = base + 2; }
            if (v.w) { int s = atomicAdd(&cnt[1], 1); idx[1][s] = base + 3; }
        }
        int nx = it + STAGES;
        if (nx < 2 * ROW_ITERS)
            CP_ASYNC16(buf_base + (((nx % STAGES) * 256 + tid) << 4), bsrc + (nx - ROW_ITERS) * 256);
        CP_COMMIT();
    }
    __syncthreads();            // all ring reads done; safe to re-alias pool
    const int bc = cnt[1];

    // pool re-aliased: red [2][4][64] float4 (8 KB) + hid [512] floats (2 KB)
    float4* red = reinterpret_cast<float4*>(pool);
    float*  hid = reinterpret_cast<float*>(pool + 8192);

    // ---- tail: black gather ----
#pragma unroll 4
    for (int j = fg; j < bc; j += 4) {
        float4 t = ftw4[(size_t)idx[1][j] * 64 + c];
        ab.x += t.x; ab.y += t.y; ab.z += t.z; ab.w += t.w;
    }
    red[(0 * 4 + fg) * 64 + c] = aw;
    red[(1 * 4 + fg) * 64 + c] = ab;
    __syncthreads();

    const bool s = (stm[b] != 0.f);

    if (tid < 128) {
        int p  = tid >> 6;
        int cc = tid & 63;
        float4 v0 = red[(p * 4 + 0) * 64 + cc], v1 = red[(p * 4 + 1) * 64 + cc];
        float4 v2 = red[(p * 4 + 2) * 64 + cc], v3 = red[(p * 4 + 3) * 64 + cc];
        float4 bi = reinterpret_cast<const float4*>(ft_b)[cc];
        float4 r;
        r.x = fminf(fmaxf(v0.x + v1.x + v2.x + v3.x + bi.x, 0.f), 1.f);
        r.y = fminf(fmaxf(v0.y + v1.y + v2.y + v3.y + bi.y, 0.f), 1.f);
        r.z = fminf(fmaxf(v0.z + v1.z + v2.z + v3.z + bi.z, 0.f), 1.f);
        r.w = fminf(fmaxf(v0.w + v1.w + v2.w + v3.w + bi.w, 0.f), 1.f);
        int half = ((p == 0) == s) ? 0 : 1;
        reinterpret_cast<float4*>(hid)[half * 64 + cc] = r;
    }
    __syncthreads();

    // ---- MLP ----
    // Layer 1: 512 -> 32, 8 threads per output
    {
        int k  = tid >> 3;
        int s8 = tid & 7;
        const float* w = l1w + k * 512;
        float p = 0.f;
#pragma unroll
        for (int j = s8; j < 512; j += 8) p += hid[j] * w[j];
        p += __shfl_down_sync(0xffffffffu, p, 4, 8);
        p += __shfl_down_sync(0xffffffffu, p, 2, 8);
        p += __shfl_down_sync(0xffffffffu, p, 1, 8);
        if (s8 == 0) x1s[k] = fminf(fmaxf(p + l1b[k], 0.f), 1.f);
    }
    __syncthreads();

    // Layer 2: 32 -> 32
    if (tid < 32) {
        float p = l2b[tid];
        const float* w = l2w + tid * 32;
#pragma unroll
        for (int j = 0; j < 32; ++j) p += x1s[j] * w[j];
        x2s[tid] = fminf(fmaxf(p, 0.f), 1.f);
    }
    __syncwarp(0xffffffffu);

    // Layer 3: 32 -> 1
    if (tid < 32) {
        float p = x2s[tid] * l3w[tid];
        p += __shfl_down_sync(0xffffffffu, p, 16);
        p += __shfl_down_sync(0xffffffffu, p, 8);
        p += __shfl_down_sync(0xffffffffu, p, 4);
        p += __shfl_down_sync(0xffffffffu, p, 2);
        p += __shfl_down_sync(0xffffffffu, p, 1);
        if (tid == 0) out[b] = p + l3b[0];
    }
}

// ---------------------------------------------------------------------------
// Launch
// ---------------------------------------------------------------------------
extern "C" void kernel_launch(void* const* d_in, const int* in_sizes, int n_in,
                              void* d_out, int out_size) {
    const float* white = (const float*)d_in[0];
    const float* black = (const float*)d_in[1];
    const float* stm   = (const float*)d_in[2];
    const float* ft_w  = (const float*)d_in[3];
    const float* ft_b  = (const float*)d_in[4];
    const float* l1w   = (const float*)d_in[5];
    const float* l1b   = (const float*)d_in[6];
    const float* l2w   = (const float*)d_in[7];
    const float* l2b   = (const float*)d_in[8];
    const float* l3w   = (const float*)d_in[9];
    const float* l3b   = (const float*)d_in[10];
    float* out = (float*)d_out;

    dim3 tb(32, 8);
    dim3 tg(IN_SZ / 32, HID / 32);
    transpose_ft<<<tg, tb>>>(ft_w);

    nnue_fused<<<BATCH, 256>>>(white, black, stm, ft_b,
                               l1w, l1b, l2w, l2b, l3w, l3b, out);
}

// round 14
// speedup vs baseline: 1.1394x; 1.1394x over previous
#include <cuda_runtime.h>

#define BATCH 2048
#define IN_SZ 40960
#define HID 256
#define NT 512                       // threads per CTA
#define ROW_F4 (IN_SZ / 4)           // 10240 uint4 per one-hot row
#define ROW_ITERS (ROW_F4 / NT)      // 20 uint4-groups per thread per perspective

__device__ float g_ftw_t[(size_t)IN_SZ * HID];   // 41.9 MB transposed weights

// ---------------------------------------------------------------------------
// Kernel 1: transpose ft_w [256, 40960] -> g_ftw_t [40960, 256]
// ---------------------------------------------------------------------------
__global__ __launch_bounds__(256) void transpose_ft(const float* __restrict__ ft_w) {
    __shared__ float tile[32][33];
    int x = blockIdx.x * 32 + threadIdx.x;
    int y = blockIdx.y * 32 + threadIdx.y;
#pragma unroll
    for (int k = 0; k < 32; k += 8)
        tile[threadIdx.y + k][threadIdx.x] = ft_w[(size_t)(y + k) * IN_SZ + x];
    __syncthreads();
    int ox = blockIdx.y * 32 + threadIdx.x;
    int oy = blockIdx.x * 32 + threadIdx.y;
#pragma unroll
    for (int k = 0; k < 32; k += 8)
        g_ftw_t[(size_t)(oy + k) * HID + ox] = tile[threadIdx.x][threadIdx.y + k];
}

// ---------------------------------------------------------------------------
// Kernel 2: one CTA (512 threads) per row; 4 CTAs/SM, 3.46 waves.
//   Wider CTA halves the per-row tail (8-way gather parallelism) and
//   increases wave stagger for tail coverage.
// ---------------------------------------------------------------------------
__global__ __launch_bounds__(NT, 4) void nnue_fused(
    const float* __restrict__ white, const float* __restrict__ black,
    const float* __restrict__ stm,
    const float* __restrict__ ft_b,
    const float* __restrict__ l1w, const float* __restrict__ l1b,
    const float* __restrict__ l2w, const float* __restrict__ l2b,
    const float* __restrict__ l3w, const float* __restrict__ l3b,
    float* __restrict__ out)
{
    const int b   = blockIdx.x;
    const int tid = threadIdx.x;

    __shared__ int    cnt[2];
    __shared__ int    idx[2][32];
    __shared__ float4 red[2][8][64];   // [persp][fgroup][col]  16 KB
    __shared__ float  hid[2 * HID];
    __shared__ float  x1s[32];
    __shared__ float  x2s[32];

    if (tid < 2) cnt[tid] = 0;
    __syncthreads();

    const int c  = tid & 63;
    const int fg = tid >> 6;           // 0..7
    const float4* __restrict__ ftw4 = reinterpret_cast<const float4*>(g_ftw_t);

    // ---- Phase A: scan white, batch-4 streaming loads ----
    {
        const uint4* src = reinterpret_cast<const uint4*>(white) + (size_t)b * ROW_F4;
        for (int it = 0; it < ROW_ITERS; it += 4) {
            uint4 f[4];
#pragma unroll
            for (int u = 0; u < 4; ++u)
                f[u] = __ldcs(&src[(it + u) * NT + tid]);
#pragma unroll
            for (int u = 0; u < 4; ++u) {
                if (f[u].x | f[u].y | f[u].z | f[u].w) {
                    int base = ((it + u) * NT + tid) * 4;
                    if (f[u].x) { int s = atomicAdd(&cnt[0], 1); idx[0][s] = base + 0; }
                    if (f[u].y) { int s = atomicAdd(&cnt[0], 1); idx[0][s] = base + 1; }
                    if (f[u].z) { int s = atomicAdd(&cnt[0], 1); idx[0][s] = base + 2; }
                    if (f[u].w) { int s = atomicAdd(&cnt[0], 1); idx[0][s] = base + 3; }
                }
            }
        }
    }
    __syncthreads();
    const int wc = cnt[0];

    // ---- Phase B: scan black, white gather interleaved ----
    float4 aw = make_float4(0.f, 0.f, 0.f, 0.f);
    float4 ab = make_float4(0.f, 0.f, 0.f, 0.f);
    {
        const uint4* src = reinterpret_cast<const uint4*>(black) + (size_t)b * ROW_F4;
        int g = 0;
        for (int it = 0; it < ROW_ITERS; it += 4) {
            uint4 f[4];
#pragma unroll
            for (int u = 0; u < 4; ++u)
                f[u] = __ldcs(&src[(it + u) * NT + tid]);
            // one white-gather step per iteration (4 steps cover wc <= 32)
            {
                int k = fg + 8 * g;
                if (k < wc) {
                    float4 v = ftw4[(size_t)idx[0][k] * 64 + c];
                    aw.x += v.x; aw.y += v.y; aw.z += v.z; aw.w += v.w;
                }
                ++g;
            }
#pragma unroll
            for (int u = 0; u < 4; ++u) {
                if (f[u].x | f[u].y | f[u].z | f[u].w) {
                    int base = ((it + u) * NT + tid) * 4;
                    if (f[u].x) { int s = atomicAdd(&cnt[1], 1); idx[1][s] = base + 0; }
                    if (f[u].y) { int s = atomicAdd(&cnt[1], 1); idx[1][s] = base + 1; }
                    if (f[u].z) { int s = atomicAdd(&cnt[1], 1); idx[1][s] = base + 2; }
                    if (f[u].w) { int s = atomicAdd(&cnt[1], 1); idx[1][s] = base + 3; }
                }
            }
        }
    }
    __syncthreads();
    const int bc = cnt[1];

    // ---- Tail: black gather (8-way feature parallelism, ~4-deep chain) ----
#pragma unroll 4
    for (int j = fg; j < bc; j += 8) {
        float4 v = ftw4[(size_t)idx[1][j] * 64 + c];
        ab.x += v.x; ab.y += v.y; ab.z += v.z; ab.w += v.w;
    }
    red[0][fg][c] = aw;
    red[1][fg][c] = ab;
    __syncthreads();

    const bool s = (stm[b] != 0.f);

    if (tid < 128) {
        int p  = tid >> 6;
        int cc = tid & 63;
        float4 bi = reinterpret_cast<const float4*>(ft_b)[cc];
        float4 t0 = red[p][0][cc];
#pragma unroll
        for (int q = 1; q < 8; ++q) {
            float4 v = red[p][q][cc];
            t0.x += v.x; t0.y += v.y; t0.z += v.z; t0.w += v.w;
        }
        float4 r;
        r.x = fminf(fmaxf(t0.x + bi.x, 0.f), 1.f);
        r.y = fminf(fmaxf(t0.y + bi.y, 0.f), 1.f);
        r.z = fminf(fmaxf(t0.z + bi.z, 0.f), 1.f);
        r.w = fminf(fmaxf(t0.w + bi.w, 0.f), 1.f);
        int half = ((p == 0) == s) ? 0 : 1;
        reinterpret_cast<float4*>(hid)[half * 64 + cc] = r;
    }
    __syncthreads();

    // ---- MLP ----
    // Layer 1: 512 -> 32, 16 threads per output
    {
        int k   = tid >> 4;            // output 0..31
        int s16 = tid & 15;
        const float* w = l1w + k * 512;
        float p = 0.f;
#pragma unroll
        for (int j = s16; j < 512; j += 16) p += hid[j] * w[j];
        p += __shfl_down_sync(0xffffffffu, p, 8, 16);
        p += __shfl_down_sync(0xffffffffu, p, 4, 16);
        p += __shfl_down_sync(0xffffffffu, p, 2, 16);
        p += __shfl_down_sync(0xffffffffu, p, 1, 16);
        if (s16 == 0) x1s[k] = fminf(fmaxf(p + l1b[k], 0.f), 1.f);
    }
    __syncthreads();

    // Layer 2: 32 -> 32
    if (tid < 32) {
        float p = l2b[tid];
        const float* w = l2w + tid * 32;
#pragma unroll
        for (int j = 0; j < 32; ++j) p += x1s[j] * w[j];
        x2s[tid] = fminf(fmaxf(p, 0.f), 1.f);
    }
    __syncwarp(0xffffffffu);

    // Layer 3: 32 -> 1
    if (tid < 32) {
        float p = x2s[tid] * l3w[tid];
        p += __shfl_down_sync(0xffffffffu, p, 16);
        p += __shfl_down_sync(0xffffffffu, p, 8);
        p += __shfl_down_sync(0xffffffffu, p, 4);
        p += __shfl_down_sync(0xffffffffu, p, 2);
        p += __shfl_down_sync(0xffffffffu, p, 1);
        if (tid == 0) out[b] = p + l3b[0];
    }
}

// ---------------------------------------------------------------------------
// Launch
// ---------------------------------------------------------------------------
extern "C" void kernel_launch(void* const* d_in, const int* in_sizes, int n_in,
                              void* d_out, int out_size) {
    const float* white = (const float*)d_in[0];
    const float* black = (const float*)d_in[1];
    const float* stm   = (const float*)d_in[2];
    const float* ft_w  = (const float*)d_in[3];
    const float* ft_b  = (const float*)d_in[4];
    const float* l1w   = (const float*)d_in[5];
    const float* l1b   = (const float*)d_in[6];
    const float* l2w   = (const float*)d_in[7];
    const float* l2b   = (const float*)d_in[8];
    const float* l3w   = (const float*)d_in[9];
    const float* l3b   = (const float*)d_in[10];
    float* out = (float*)d_out;

    dim3 tb(32, 8);
    dim3 tg(IN_SZ / 32, HID / 32);
    transpose_ft<<<tg, tb>>>(ft_w);

    nnue_fused<<<BATCH, NT>>>(white, black, stm, ft_b,
                              l1w, l1b, l2w, l2b, l3w, l3b, out);
}